// round 3
// baseline (speedup 1.0000x reference)
#include <cuda_runtime.h>
#include <cstdint>

// ============================================================================
// Persistent 2-layer LSTM for GB300 (sm_103a).
//   batch=32 (= warp lanes), seq=1024, in=256, hid=out=512, fp32.
//   148 persistent CTAs; each owns 3-4 LSTM units (all 4 gates) per layer.
//   Weights resident in SMEM as (f,i)/(c,o) float2 pairs; inner loop uses
//   fma.rn.f32x2 (packed fp32 FMA). h state ping-pongs through L2
//   (__device__ buffers), staged into SMEM with cp.async.cg (L1 bypass).
//   Two release/acquire software grid barriers per timestep.
// ============================================================================

#define NCTA 148
#define SMEM_W0   0                 // [768][8] float2  = 49152 B
#define SMEM_W1   49152             // [1024][8] float2 = 65536 B
#define SMEM_HB   114688            // 2 x (256*32) floats = 65536 B
#define SMEM_RED  180224            // 8 warps x 8 pairs x 32 lanes x 8B = 16384 B
#define SMEM_TOTAL 196608

// ------------------------- device-global scratch ---------------------------
__device__ float g_xT[1024 * 256 * 32];            // x transposed: [t][c][b]
__device__ float g_h[2][2][512][32];               // [layer][parity][unit][batch]
__device__ float2 g_w0[(size_t)NCTA * 768 * 8];    // per-CTA weight images, layer0
__device__ float2 g_w1[(size_t)NCTA * 1024 * 8];   // per-CTA weight images, layer1
__device__ unsigned g_bar;                         // grid barrier counter

// ------------------------------ helpers ------------------------------------
static __device__ __forceinline__ void cp16(void* d, const void* s) {
    unsigned ds = (unsigned)__cvta_generic_to_shared(d);
    asm volatile("cp.async.cg.shared.global [%0], [%1], 16;" :: "r"(ds), "l"(s));
}
static __device__ __forceinline__ float sigm(float x) {
    return 1.0f / (1.0f + __expf(-x));
}
static __device__ __forceinline__ float tanh_f(float x) {
    return 1.0f - 2.0f / (__expf(2.0f * x) + 1.0f);
}
static __device__ __forceinline__ unsigned long long pk(unsigned lo, unsigned hi) {
    unsigned long long r;
    asm("mov.b64 %0, {%1, %2};" : "=l"(r) : "r"(lo), "r"(hi));
    return r;
}
static __device__ __forceinline__ void ffma2(unsigned long long& acc,
                                             unsigned long long a,
                                             unsigned long long b) {
    asm("fma.rn.f32x2 %0, %1, %2, %0;" : "+l"(acc) : "l"(a), "l"(b));
}

// stage one 32KB chunk (256 k-rows x 32 batch floats) global -> shared
static __device__ __forceinline__ void stage(float* dst, const float* src, int tid) {
    #pragma unroll
    for (int i = 0; i < 8; i++)
        cp16((char*)dst + tid * 16 + i * 4096, (const char*)src + tid * 16 + i * 4096);
    asm volatile("cp.async.commit_group;" ::: "memory");
}

// software grid barrier (release/acquire, gpu scope)
static __device__ __forceinline__ void grid_bar(unsigned& target) {
    __syncthreads();
    target += NCTA;
    if (threadIdx.x == 0) {
        __threadfence();
        unsigned* bp = &g_bar;
        asm volatile("red.release.gpu.global.add.u32 [%0], 1;" :: "l"(bp) : "memory");
        unsigned v;
        for (;;) {
            asm volatile("ld.acquire.gpu.global.u32 %0, [%1];" : "=r"(v) : "l"(bp) : "memory");
            if ((int)(v - target) >= 0) break;
            __nanosleep(32);
        }
    }
    __syncthreads();
}

// matmul phase: acc2[p] += sum_k combined[k][lane] * w2[k][p]  (f32x2 pairs)
static __device__ __forceinline__ void phase_mm(
    const uint4* __restrict__ wv,      // SMEM weights: [K][4] uint4 (=8 f32 pairs)
    float* __restrict__ hb,            // 2 x 8192 floats (double buffer)
    const float* s0, const float* s1, const float* s2, const float* s3,
    int nch, int lane, int warp, int tid, unsigned long long acc[8])
{
    const float* srcs[4] = { s0, s1, s2, s3 };
    #pragma unroll
    for (int p = 0; p < 8; p++) acc[p] = 0ULL;

    stage(hb, srcs[0], tid);
    for (int ci = 0; ci < nch; ci++) {
        if (ci + 1 < nch) {
            stage(hb + ((ci + 1) & 1) * 8192, srcs[ci + 1], tid);
            asm volatile("cp.async.wait_group 1;" ::: "memory");
        } else {
            asm volatile("cp.async.wait_group 0;" ::: "memory");
        }
        __syncthreads();
        const float* hp = hb + (ci & 1) * 8192 + warp * 1024 + lane;
        const uint4* wp = wv + (size_t)(ci * 256 + warp * 32) * 4;
        #pragma unroll 4
        for (int kk = 0; kk < 32; kk++) {
            float h = hp[kk * 32];
            unsigned hu = __float_as_uint(h);
            unsigned long long h2 = pk(hu, hu);
            uint4 wa = wp[kk * 4 + 0];
            uint4 wb = wp[kk * 4 + 1];
            uint4 wc = wp[kk * 4 + 2];
            uint4 wd = wp[kk * 4 + 3];
            ffma2(acc[0], h2, pk(wa.x, wa.y));
            ffma2(acc[1], h2, pk(wa.z, wa.w));
            ffma2(acc[2], h2, pk(wb.x, wb.y));
            ffma2(acc[3], h2, pk(wb.z, wb.w));
            ffma2(acc[4], h2, pk(wc.x, wc.y));
            ffma2(acc[5], h2, pk(wc.z, wc.w));
            ffma2(acc[6], h2, pk(wd.x, wd.y));
            ffma2(acc[7], h2, pk(wd.z, wd.w));
        }
        __syncthreads();   // buffer half is overwritten by prefetch next iter
    }
}

// --------------------------- persistent kernel -----------------------------
__global__ void __launch_bounds__(256, 1)
lstm_persist(const float* __restrict__ b0f, const float* __restrict__ b0i,
             const float* __restrict__ b0c, const float* __restrict__ b0o,
             const float* __restrict__ b1f, const float* __restrict__ b1i,
             const float* __restrict__ b1c, const float* __restrict__ b1o,
             float* __restrict__ out)
{
    extern __shared__ char smem[];
    const uint4* w0 = (const uint4*)(smem + SMEM_W0);
    const uint4* w1 = (const uint4*)(smem + SMEM_W1);
    float*       hb = (float*)(smem + SMEM_HB);
    float2*      red = (float2*)(smem + SMEM_RED);
    unsigned long long* redu = (unsigned long long*)red;

    const int tid  = threadIdx.x;
    const int lane = tid & 31;       // = batch index
    const int warp = tid >> 5;
    const int cta  = blockIdx.x;
    const int U     = (cta < 68) ? 4 : 3;                       // 68*4+80*3=512
    const int ubase = (cta < 68) ? 4 * cta : 272 + 3 * (cta - 68);

    // load this CTA's weight images into SMEM (once)
    {
        const char* s0 = (const char*)(g_w0 + (size_t)cta * 768 * 8);
        #pragma unroll
        for (int i = 0; i < 12; i++)
            cp16((char*)smem + SMEM_W0 + tid * 16 + i * 4096, s0 + tid * 16 + i * 4096);
        const char* s1 = (const char*)(g_w1 + (size_t)cta * 1024 * 8);
        #pragma unroll
        for (int i = 0; i < 16; i++)
            cp16((char*)smem + SMEM_W1 + tid * 16 + i * 4096, s1 + tid * 16 + i * 4096);
        asm volatile("cp.async.commit_group;" ::: "memory");
        asm volatile("cp.async.wait_group 0;" ::: "memory");
    }
    __syncthreads();

    // each warp finalizes exactly one unit of one layer (warps 0-3: L0, 4-7: L1)
    const int j  = warp & 3;
    const int Lw = warp >> 2;
    const int uu = ubase + (j < U ? j : 0);
    const float Bf = Lw ? b1f[uu] : b0f[uu];
    const float Bi = Lw ? b1i[uu] : b0i[uu];
    const float Bc = Lw ? b1c[uu] : b0c[uu];
    const float Bo = Lw ? b1o[uu] : b0o[uu];
    float cst = 0.0f;                       // cell state lives in a register
    unsigned target = 0;
    unsigned long long acc[8];

    for (int t = 0; t < 1024; t++) {
        const int par = t & 1, par2 = par ^ 1;

        // ---------------- layer 0: K = 768 = [x_t(256); h0(512)] -----------
        {
            const float* xs = g_xT + (size_t)t * 8192;
            const float* h0 = &g_h[0][par][0][0];
            phase_mm(w0, hb, xs, h0, h0 + 8192, nullptr, 3, lane, warp, tid, acc);

            #pragma unroll
            for (int p = 0; p < 8; p++) redu[(warp * 8 + p) * 32 + lane] = acc[p];
            __syncthreads();

            if (Lw == 0) {
                float2 sfi = make_float2(0.f, 0.f), sco = make_float2(0.f, 0.f);
                #pragma unroll
                for (int w = 0; w < 8; w++) {
                    float2 a = red[(w * 8 + 2 * j) * 32 + lane];
                    float2 b = red[(w * 8 + 2 * j + 1) * 32 + lane];
                    sfi.x += a.x; sfi.y += a.y; sco.x += b.x; sco.y += b.y;
                }
                float f  = sigm(sfi.x + Bf);
                float ig = sigm(sfi.y + Bi);
                float gg = tanh_f(sco.x + Bc);
                float o  = sigm(sco.y + Bo);
                cst = f * cst + ig * gg;
                float h = o * tanh_f(cst);
                if (j < U) g_h[0][par2][ubase + j][lane] = h;
            }
            grid_bar(target);
        }

        // ---------------- layer 1: K = 1024 = [h0_new(512); h1(512)] -------
        {
            const float* h0 = &g_h[0][par2][0][0];
            const float* h1 = &g_h[1][par][0][0];
            phase_mm(w1, hb, h0, h0 + 8192, h1, h1 + 8192, 4, lane, warp, tid, acc);

            #pragma unroll
            for (int p = 0; p < 8; p++) redu[(warp * 8 + p) * 32 + lane] = acc[p];
            __syncthreads();

            if (Lw == 1) {
                float2 sfi = make_float2(0.f, 0.f), sco = make_float2(0.f, 0.f);
                #pragma unroll
                for (int w = 0; w < 8; w++) {
                    float2 a = red[(w * 8 + 2 * j) * 32 + lane];
                    float2 b = red[(w * 8 + 2 * j + 1) * 32 + lane];
                    sfi.x += a.x; sfi.y += a.y; sco.x += b.x; sco.y += b.y;
                }
                float f  = sigm(sfi.x + Bf);
                float ig = sigm(sfi.y + Bi);
                float gg = tanh_f(sco.x + Bc);
                float o  = sigm(sco.y + Bo);
                cst = f * cst + ig * gg;
                float h = o * tanh_f(cst);
                if (j < U) {
                    int u = ubase + j;
                    g_h[1][par2][u][lane] = h;
                    out[(size_t)lane * 524288 + (size_t)t * 512 + u] = h;
                }
            }
            grid_bar(target);
        }
    }
}

// ------------------------------ prep kernels -------------------------------
__global__ void init_kernel() {
    int idx = blockIdx.x * blockDim.x + threadIdx.x;
    if (idx == 0) g_bar = 0u;
    if (idx < 2 * 2 * 512 * 32) (&g_h[0][0][0][0])[idx] = 0.f;
}

__global__ void transpose_x_kernel(const float* __restrict__ x) {
    int idx = blockIdx.x * blockDim.x + threadIdx.x;     // t*8192 + c*32 + b
    int b = idx & 31;
    int c = (idx >> 5) & 255;
    int t = idx >> 13;
    g_xT[idx] = x[b * 262144 + t * 256 + c];
}

__global__ void prep_w_kernel(int layer,
                              const float* __restrict__ Wf, const float* __restrict__ Wi,
                              const float* __restrict__ Wc, const float* __restrict__ Wo,
                              int K)
{
    long idx = (long)blockIdx.x * blockDim.x + threadIdx.x;
    long total = (long)NCTA * K * 8;
    if (idx >= total) return;
    int  p   = (int)(idx & 7);
    long r   = idx >> 3;
    int  k   = (int)(r % K);
    int  cta = (int)(r / K);
    int  U     = (cta < 68) ? 4 : 3;
    int  ubase = (cta < 68) ? 4 * cta : 272 + 3 * (cta - 68);
    int  jj = p >> 1, q = p & 1;
    float2 v = make_float2(0.f, 0.f);
    if (jj < U) {
        size_t o = (size_t)(ubase + jj) * K + k;
        v = q ? make_float2(Wc[o], Wo[o]) : make_float2(Wf[o], Wi[o]);
    }
    if (layer) g_w1[idx] = v; else g_w0[idx] = v;
}

// ------------------------------- launcher ----------------------------------
extern "C" void kernel_launch(void* const* d_in, const int* in_sizes, int n_in,
                              void* d_out, int out_size)
{
    const float* x   = (const float*)d_in[0];
    const float* W0f = (const float*)d_in[1];
    const float* b0f = (const float*)d_in[2];
    const float* W0i = (const float*)d_in[3];
    const float* b0i = (const float*)d_in[4];
    const float* W0c = (const float*)d_in[5];
    const float* b0c = (const float*)d_in[6];
    const float* W0o = (const float*)d_in[7];
    const float* b0o = (const float*)d_in[8];
    const float* W1f = (const float*)d_in[9];
    const float* b1f = (const float*)d_in[10];
    const float* W1i = (const float*)d_in[11];
    const float* b1i = (const float*)d_in[12];
    const float* W1c = (const float*)d_in[13];
    const float* b1c = (const float*)d_in[14];
    const float* W1o = (const float*)d_in[15];
    const float* b1o = (const float*)d_in[16];
    float* out = (float*)d_out;

    cudaFuncSetAttribute(lstm_persist,
                         cudaFuncAttributeMaxDynamicSharedMemorySize, SMEM_TOTAL);

    init_kernel<<<256, 256>>>();
    transpose_x_kernel<<<(1024 * 256 * 32) / 256, 256>>>(x);
    {
        long t0 = (long)NCTA * 768 * 8;
        prep_w_kernel<<<(unsigned)((t0 + 255) / 256), 256>>>(0, W0f, W0i, W0c, W0o, 768);
        long t1 = (long)NCTA * 1024 * 8;
        prep_w_kernel<<<(unsigned)((t1 + 255) / 256), 256>>>(1, W1f, W1i, W1c, W1o, 1024);
    }
    lstm_persist<<<NCTA, 256, SMEM_TOTAL>>>(b0f, b0i, b0c, b0o,
                                            b1f, b1i, b1c, b1o, out);
}

// round 4
// speedup vs baseline: 1.0606x; 1.0606x over previous
#include <cuda_runtime.h>
#include <cstdint>

// ============================================================================
// Persistent 2-layer LSTM for GB300 (sm_103a) — R4.
//   batch=32 (= warp lanes), seq=1024, in=256, hid=out=512, fp32.
//   148 persistent CTAs; each owns 3-4 LSTM units (all 4 gates) per layer.
//   Weights resident in SMEM as (f,i)/(c,o) float2 pairs; inner loop uses
//   fma.rn.f32x2. h state ping-pongs through L2 (__device__ buffers).
//   R4: 3-slot rotating prefetch schedule — every chunk is staged one phase
//   ahead of use (only L1's h0-new chunks are staged post-barrier, hidden
//   behind 2 chunks of prefetched compute); h0-new slots are RETAINED and
//   reused as next step's L0 h0-old (saves 64KB/CTA/step of L2 traffic).
//   Single fused prep kernel so ncu (-s 5) profiles lstm_persist.
// ============================================================================

#define NCTA 148
#define SMEM_W0   0                 // [768][8] float2  = 49152 B
#define SMEM_W1   49152             // [1024][8] float2 = 65536 B
#define SMEM_RED  114688            // 8 warps x 8 pairs x 32 lanes x 8B = 16384 B
#define SMEM_SLOT 131072            // 3 x 32768 B staging slots
#define SMEM_TOTAL 229376           // 224 KB

// ------------------------- device-global scratch ---------------------------
__device__ float g_xT[1024 * 256 * 32];            // x transposed: [t][c][b]
__device__ float g_h[2][2][512][32];               // [layer][parity][unit][batch]
__device__ float2 g_w0[(size_t)NCTA * 768 * 8];    // per-CTA weight images, layer0
__device__ float2 g_w1[(size_t)NCTA * 1024 * 8];   // per-CTA weight images, layer1
__device__ unsigned g_bar;                         // grid barrier counter

// ------------------------------ helpers ------------------------------------
static __device__ __forceinline__ void cp16(void* d, const void* s) {
    unsigned ds = (unsigned)__cvta_generic_to_shared(d);
    asm volatile("cp.async.cg.shared.global [%0], [%1], 16;" :: "r"(ds), "l"(s));
}
static __device__ __forceinline__ float sigm(float x) {
    return 1.0f / (1.0f + __expf(-x));
}
static __device__ __forceinline__ float tanh_f(float x) {
    return 1.0f - 2.0f / (__expf(2.0f * x) + 1.0f);
}
static __device__ __forceinline__ unsigned long long pk(unsigned lo, unsigned hi) {
    unsigned long long r;
    asm("mov.b64 %0, {%1, %2};" : "=l"(r) : "r"(lo), "r"(hi));
    return r;
}
static __device__ __forceinline__ void ffma2(unsigned long long& acc,
                                             unsigned long long a,
                                             unsigned long long b) {
    asm("fma.rn.f32x2 %0, %1, %2, %0;" : "+l"(acc) : "l"(a), "l"(b));
}
#define WAITG(n) asm volatile("cp.async.wait_group %0;" :: "n"(n) : "memory")

// stage one 32KB chunk (256 k-rows x 32 batch floats) global -> shared; 1 group
static __device__ __forceinline__ void stage(float* dst, const float* src, int tid) {
    #pragma unroll
    for (int i = 0; i < 8; i++)
        cp16((char*)dst + tid * 16 + i * 4096, (const char*)src + tid * 16 + i * 4096);
    asm volatile("cp.async.commit_group;" ::: "memory");
}

// software grid barrier (release/acquire, gpu scope)
static __device__ __forceinline__ void grid_bar(unsigned& target) {
    __syncthreads();
    target += NCTA;
    if (threadIdx.x == 0) {
        __threadfence();
        unsigned* bp = &g_bar;
        asm volatile("red.release.gpu.global.add.u32 [%0], 1;" :: "l"(bp) : "memory");
        unsigned v;
        for (;;) {
            asm volatile("ld.acquire.gpu.global.u32 %0, [%1];" : "=r"(v) : "l"(bp) : "memory");
            if ((int)(v - target) >= 0) break;
            __nanosleep(32);
        }
    }
    __syncthreads();
}

// one 256-k chunk of the matmul: acc[p] += sum_k h[k][lane] * w2[ko+k][p]
static __device__ __forceinline__ void compute_chunk(
    const uint4* __restrict__ wv, const float* __restrict__ slot,
    int ko, int lane, int warp, unsigned long long acc[8])
{
    const float* hp = slot + warp * 1024 + lane;
    const uint4* wp = wv + (size_t)(ko + warp * 32) * 4;
    #pragma unroll 4
    for (int kk = 0; kk < 32; kk++) {
        float h = hp[kk * 32];
        unsigned hu = __float_as_uint(h);
        unsigned long long h2 = pk(hu, hu);
        uint4 wa = wp[kk * 4 + 0];
        uint4 wb = wp[kk * 4 + 1];
        uint4 wc = wp[kk * 4 + 2];
        uint4 wd = wp[kk * 4 + 3];
        ffma2(acc[0], h2, pk(wa.x, wa.y));
        ffma2(acc[1], h2, pk(wa.z, wa.w));
        ffma2(acc[2], h2, pk(wb.x, wb.y));
        ffma2(acc[3], h2, pk(wb.z, wb.w));
        ffma2(acc[4], h2, pk(wc.x, wc.y));
        ffma2(acc[5], h2, pk(wc.z, wc.w));
        ffma2(acc[6], h2, pk(wd.x, wd.y));
        ffma2(acc[7], h2, pk(wd.z, wd.w));
    }
}

// --------------------------- persistent kernel -----------------------------
__global__ void __launch_bounds__(256, 1)
lstm_persist(const float* __restrict__ b0f, const float* __restrict__ b0i,
             const float* __restrict__ b0c, const float* __restrict__ b0o,
             const float* __restrict__ b1f, const float* __restrict__ b1i,
             const float* __restrict__ b1c, const float* __restrict__ b1o,
             float* __restrict__ out)
{
    extern __shared__ char smem[];
    const uint4* w0 = (const uint4*)(smem + SMEM_W0);
    const uint4* w1 = (const uint4*)(smem + SMEM_W1);
    float2*      red = (float2*)(smem + SMEM_RED);
    unsigned long long* redu = (unsigned long long*)red;
    float* slot[3] = { (float*)(smem + SMEM_SLOT),
                       (float*)(smem + SMEM_SLOT) + 8192,
                       (float*)(smem + SMEM_SLOT) + 16384 };

    const int tid  = threadIdx.x;
    const int lane = tid & 31;       // = batch index
    const int warp = tid >> 5;
    const int cta  = blockIdx.x;
    const int U     = (cta < 68) ? 4 : 3;                       // 68*4+80*3=512
    const int ubase = (cta < 68) ? 4 * cta : 272 + 3 * (cta - 68);

    // load this CTA's weight images into SMEM (once)
    {
        const char* s0 = (const char*)(g_w0 + (size_t)cta * 768 * 8);
        #pragma unroll
        for (int i = 0; i < 12; i++)
            cp16((char*)smem + SMEM_W0 + tid * 16 + i * 4096, s0 + tid * 16 + i * 4096);
        const char* s1 = (const char*)(g_w1 + (size_t)cta * 1024 * 8);
        #pragma unroll
        for (int i = 0; i < 16; i++)
            cp16((char*)smem + SMEM_W1 + tid * 16 + i * 4096, s1 + tid * 16 + i * 4096);
        asm volatile("cp.async.commit_group;" ::: "memory");
    }

    // each warp finalizes exactly one unit of one layer (warps 0-3: L0, 4-7: L1)
    const int j  = warp & 3;
    const int Lw = warp >> 2;
    const int uu = ubase + (j < U ? j : 0);
    const float Bf = Lw ? b1f[uu] : b0f[uu];
    const float Bi = Lw ? b1i[uu] : b0i[uu];
    const float Bc = Lw ? b1c[uu] : b0c[uu];
    const float Bo = Lw ? b1o[uu] : b0o[uu];
    float cst = 0.0f;                       // cell state lives in a register
    unsigned target = 0;
    unsigned long long acc[8];

    // prologue: preload step-0 L0 chunks (x(0), h0=zeros) into slots 0..2
    stage(slot[0], g_xT, tid);
    stage(slot[1], &g_h[0][0][0][0], tid);
    stage(slot[2], &g_h[0][0][256][0], tid);
    WAITG(0);
    __syncthreads();

    int base = 0;
    for (int t = 0; t < 1024; t++) {
        const int par = t & 1, par2 = par ^ 1;
        float* s0 = slot[base];
        float* s1 = slot[base == 2 ? 0 : base + 1];
        float* s2 = slot[base == 0 ? 2 : base - 1];

        // ============= layer 0: K = 768 = [x_t(256); h0(512)] ==============
        #pragma unroll
        for (int p = 0; p < 8; p++) acc[p] = 0ULL;
        compute_chunk(w0, s0, 0, lane, warp, acc);           // x(t)
        __syncthreads();
        stage(s0, &g_h[1][par][0][0], tid);                  // G1: h1-old a
        compute_chunk(w0, s1, 256, lane, warp, acc);         // h0-old a
        __syncthreads();
        stage(s1, &g_h[1][par][256][0], tid);                // G2: h1-old b
        compute_chunk(w0, s2, 512, lane, warp, acc);         // h0-old b

        #pragma unroll
        for (int p = 0; p < 8; p++) redu[(warp * 8 + p) * 32 + lane] = acc[p];
        __syncthreads();
        if (Lw == 0) {
            float2 sfi = make_float2(0.f, 0.f), sco = make_float2(0.f, 0.f);
            #pragma unroll
            for (int w = 0; w < 8; w++) {
                float2 a = red[(w * 8 + 2 * j) * 32 + lane];
                float2 b = red[(w * 8 + 2 * j + 1) * 32 + lane];
                sfi.x += a.x; sfi.y += a.y; sco.x += b.x; sco.y += b.y;
            }
            float f  = sigm(sfi.x + Bf);
            float ig = sigm(sfi.y + Bi);
            float gg = tanh_f(sco.x + Bc);
            float o  = sigm(sco.y + Bo);
            cst = f * cst + ig * gg;
            float h = o * tanh_f(cst);
            if (j < U) g_h[0][par2][ubase + j][lane] = h;
        }
        grid_bar(target);

        // ============= layer 1: K = 1024 = [h0-new(512); h1-old(512)] ======
        stage(s2, &g_h[0][par2][0][0], tid);                 // G3: h0-new a
        #pragma unroll
        for (int p = 0; p < 8; p++) acc[p] = 0ULL;

        WAITG(2); __syncthreads();                           // G1 done
        compute_chunk(w1, s0, 512, lane, warp, acc);         // h1-old a
        WAITG(2); __syncthreads();                           // G2 done (G3+G4? G4 not yet) -> pending {G2,G3}
        stage(s0, &g_h[0][par2][256][0], tid);               // G4: h0-new b
        compute_chunk(w1, s1, 768, lane, warp, acc);         // h1-old b
        WAITG(2); __syncthreads();                           // G3 done (pending {G4,G5?}) G5 not yet -> {G3,G4}->wait2 ok
        {
            int tn = (t + 1 < 1024) ? t + 1 : 1023;
            stage(s1, g_xT + (size_t)tn * 8192, tid);        // G5: x(t+1)
        }
        compute_chunk(w1, s2, 0, lane, warp, acc);           // h0-new a
        WAITG(1); __syncthreads();                           // G4 done (pending {G5})
        compute_chunk(w1, s0, 256, lane, warp, acc);         // h0-new b

        #pragma unroll
        for (int p = 0; p < 8; p++) redu[(warp * 8 + p) * 32 + lane] = acc[p];
        __syncthreads();
        if (Lw == 1) {
            float2 sfi = make_float2(0.f, 0.f), sco = make_float2(0.f, 0.f);
            #pragma unroll
            for (int w = 0; w < 8; w++) {
                float2 a = red[(w * 8 + 2 * j) * 32 + lane];
                float2 b = red[(w * 8 + 2 * j + 1) * 32 + lane];
                sfi.x += a.x; sfi.y += a.y; sco.x += b.x; sco.y += b.y;
            }
            float f  = sigm(sfi.x + Bf);
            float ig = sigm(sfi.y + Bi);
            float gg = tanh_f(sco.x + Bc);
            float o  = sigm(sco.y + Bo);
            cst = f * cst + ig * gg;
            float h = o * tanh_f(cst);
            if (j < U) {
                int u = ubase + j;
                g_h[1][par2][u][lane] = h;
                out[(size_t)lane * 524288 + (size_t)t * 512 + u] = h;
            }
        }
        WAITG(0);                                            // drain G5 pre-barrier
        grid_bar(target);

        // slots now hold: s1=x(t+1), s2=h0-new a, s0=h0-new b  -> base+1
        base = (base == 2) ? 0 : base + 1;
    }
}

// ------------------------------ fused prep ---------------------------------
// segments: [0, 8388608) transpose x | [.., +65536) zero g_h (+bar)
//           [.., +909312) w0 image   | [.., +1212416) w1 image
__global__ void prep_all(const float* __restrict__ x,
                         const float* __restrict__ W0f, const float* __restrict__ W0i,
                         const float* __restrict__ W0c, const float* __restrict__ W0o,
                         const float* __restrict__ W1f, const float* __restrict__ W1i,
                         const float* __restrict__ W1c, const float* __restrict__ W1o)
{
    long idx = (long)blockIdx.x * blockDim.x + threadIdx.x;
    if (idx < 8388608L) {                                   // x transpose
        int b = (int)(idx & 31);
        int c = (int)((idx >> 5) & 255);
        int t = (int)(idx >> 13);
        g_xT[idx] = x[(size_t)b * 262144 + (size_t)t * 256 + c];
        return;
    }
    idx -= 8388608L;
    if (idx < 65536L) {                                     // zero h state + bar
        if (idx == 0) g_bar = 0u;
        (&g_h[0][0][0][0])[idx] = 0.f;
        return;
    }
    idx -= 65536L;
    int layer; long widx; int K;
    const float *Wf, *Wi, *Wc, *Wo;
    if (idx < (long)NCTA * 768 * 8) {
        layer = 0; widx = idx; K = 768; Wf = W0f; Wi = W0i; Wc = W0c; Wo = W0o;
    } else {
        layer = 1; widx = idx - (long)NCTA * 768 * 8; K = 1024;
        Wf = W1f; Wi = W1i; Wc = W1c; Wo = W1o;
        if (widx >= (long)NCTA * 1024 * 8) return;
    }
    int  p   = (int)(widx & 7);
    long r   = widx >> 3;
    int  k   = (int)(r % K);
    int  cta = (int)(r / K);
    int  U     = (cta < 68) ? 4 : 3;
    int  ubase = (cta < 68) ? 4 * cta : 272 + 3 * (cta - 68);
    int  jj = p >> 1, q = p & 1;
    float2 v = make_float2(0.f, 0.f);
    if (jj < U) {
        size_t o = (size_t)(ubase + jj) * K + k;
        v = q ? make_float2(Wc[o], Wo[o]) : make_float2(Wf[o], Wi[o]);
    }
    if (layer) g_w1[widx] = v; else g_w0[widx] = v;
}

// ------------------------------- launcher ----------------------------------
extern "C" void kernel_launch(void* const* d_in, const int* in_sizes, int n_in,
                              void* d_out, int out_size)
{
    const float* x   = (const float*)d_in[0];
    const float* W0f = (const float*)d_in[1];
    const float* b0f = (const float*)d_in[2];
    const float* W0i = (const float*)d_in[3];
    const float* b0i = (const float*)d_in[4];
    const float* W0c = (const float*)d_in[5];
    const float* b0c = (const float*)d_in[6];
    const float* W0o = (const float*)d_in[7];
    const float* b0o = (const float*)d_in[8];
    const float* W1f = (const float*)d_in[9];
    const float* b1f = (const float*)d_in[10];
    const float* W1i = (const float*)d_in[11];
    const float* b1i = (const float*)d_in[12];
    const float* W1c = (const float*)d_in[13];
    const float* b1c = (const float*)d_in[14];
    const float* W1o = (const float*)d_in[15];
    const float* b1o = (const float*)d_in[16];
    float* out = (float*)d_out;

    cudaFuncSetAttribute(lstm_persist,
                         cudaFuncAttributeMaxDynamicSharedMemorySize, SMEM_TOTAL);

    // total prep items = 8388608 + 65536 + 909312 + 1212416 = 10575872 = 41312*256
    prep_all<<<41312, 256>>>(x, W0f, W0i, W0c, W0o, W1f, W1i, W1c, W1o);
    lstm_persist<<<NCTA, 256, SMEM_TOTAL>>>(b0f, b0i, b0c, b0o,
                                            b1f, b1i, b1c, b1o, out);
}